// round 14
// baseline (speedup 1.0000x reference)
#include <cuda_runtime.h>
#include <cstdint>
#include <cstddef>

// Problem constants
#define SQ 2048
#define DK 2048
#define NB 2
#define NH 32
#define NKV 8
#define HD 64

__device__ float g_q [(size_t)NB * NH  * SQ * HD];
__device__ float g_k [(size_t)NB * NKV * SQ * HD];
__device__ float g_v [(size_t)NB * NKV * SQ * HD];
__device__ float g_ao[(size_t)NB * SQ * NH * HD];

// ---------------------------------------------------------------------------
// Packed f32x2 helpers
// ---------------------------------------------------------------------------
__device__ __forceinline__ unsigned long long bcast2(float x) {
  unsigned long long r;
  unsigned int u = __float_as_uint(x);
  asm("mov.b64 %0, {%1, %1};" : "=l"(r) : "r"(u));
  return r;
}
__device__ __forceinline__ unsigned long long pack2(float x, float y) {
  unsigned long long r;
  asm("mov.b64 %0, {%1, %2};" : "=l"(r)
      : "r"(__float_as_uint(x)), "r"(__float_as_uint(y)));
  return r;
}
__device__ __forceinline__ void fma2(unsigned long long& d,
                                     unsigned long long a,
                                     unsigned long long b) {
  asm("fma.rn.f32x2 %0, %1, %2, %0;" : "+l"(d) : "l"(a), "l"(b));
}
__device__ __forceinline__ void mul2(unsigned long long& d,
                                     unsigned long long a) {
  asm("mul.rn.f32x2 %0, %0, %1;" : "+l"(d) : "l"(a));
}
__device__ __forceinline__ float2 unpack2(unsigned long long v) {
  unsigned int lo, hi;
  asm("mov.b64 {%0, %1}, %2;" : "=r"(lo), "=r"(hi) : "l"(v));
  return make_float2(__uint_as_float(lo), __uint_as_float(hi));
}

// ---------------------------------------------------------------------------
// GEMM: BM=128, BN=128, BK=16, 256 threads, 8x8 micro-tile (f32x2 packed).
// Warp map: tx = (lane&7)|((w&1)<<3)  (8 distinct tx/warp -> B reads at the
//           256B-unique floor), ty = (lane>>3)|((w>>1)<<2) (4 distinct
//           ty/warp -> A reads conflict-free).
// 2 blocks/SM (16 warps) restores latency hiding lost in the R12 attempt.
// RoPE epilogue: d^32 partner owned by lane^4 -> __shfl_xor, no smem staging.
// mode 0: row-major C write (O proj), N = 128*gridDim.x
// mode 4: fused QKV — hx in [0,16): Q (2 heads/block, rope)
//                     [16,20): K (2 kv-heads/block, rope)
//                     [20,24): V (2 kv-heads/block, plain)
// ---------------------------------------------------------------------------
struct GemmSmem {
  float As[2][16][132];   // [stage][k][m]
  float Bs[2][16][136];   // [stage][k][n]  (136 floats = 544 B, 16B-aligned)
};

__global__ void __launch_bounds__(256)
gemm128x128(const float* __restrict__ A,
            const float* __restrict__ Wq, const float* __restrict__ Wk,
            const float* __restrict__ Wv,
            float* __restrict__ Cq, float* __restrict__ Ck,
            float* __restrict__ Cv,
            const float* __restrict__ rc, const float* __restrict__ rs,
            int mode)
{
  __shared__ GemmSmem sm;
  const int tid  = threadIdx.x;
  const int w    = tid >> 5;
  const int lane = tid & 31;
  const int tx = (lane & 7) | ((w & 1) << 3);    // 0..15, col-group of 8
  const int ty = (lane >> 3) | ((w >> 1) << 2);  // 0..15, row-group of 8
  const int m0 = blockIdx.y * 128;

  // route block -> (weight, output, head-count, rope, N, head base)
  int hx = blockIdx.x;
  bool rope = false;
  const float* W = Wq;
  float* Cout = Cq;
  int H = NH;
  int N = 128 * gridDim.x;          // mode 0
  int hbase = 0;
  if (mode == 4) {
    if (hx < 16)      { W = Wq; Cout = Cq; H = NH;  rope = true;  N = 2048; hbase = 2 * hx; }
    else if (hx < 20) { hx -= 16; W = Wk; Cout = Ck; H = NKV; rope = true;  N = 512; hbase = 2 * hx; }
    else              { hx -= 20; W = Wv; Cout = Cv; H = NKV; rope = false; N = 512; hbase = 2 * hx; }
  }
  const int n0 = hx * 128;

  unsigned long long acc2[4][8];   // [row-pair][col]
#pragma unroll
  for (int i = 0; i < 4; i++)
#pragma unroll
    for (int j = 0; j < 8; j++) acc2[i][j] = 0ull;

  // Loaders:
  // A: row = tid&127, kq = (tid>>7)*8 -> 2 LDG.128, 8 scalar STS (transpose)
  // B: bK = tid>>4, bNq = (tid&15)*8 -> 2 LDG.128, 2 STS.128
  const int aRow = tid & 127;
  const int aKq  = (tid >> 7) * 8;
  const int bK   = tid >> 4;
  const int bNq  = (tid & 15) * 8;

  const float* Aptr = A + (size_t)(m0 + aRow) * DK + aKq;
  const float* Bptr = W + (size_t)bK * N + n0 + bNq;

  float4 a0 = *(const float4*)(Aptr);
  float4 a1 = *(const float4*)(Aptr + 4);
  float4 b0 = *(const float4*)(Bptr);
  float4 b1 = *(const float4*)(Bptr + 4);

  {
    const float av[8] = {a0.x,a0.y,a0.z,a0.w, a1.x,a1.y,a1.z,a1.w};
#pragma unroll
    for (int u = 0; u < 8; u++) sm.As[0][aKq + u][aRow] = av[u];
    *(float4*)&sm.Bs[0][bK][bNq] = b0;
    *(float4*)&sm.Bs[0][bK][bNq + 4] = b1;
  }
  __syncthreads();

  for (int it = 0; it < DK / 16; it++) {
    const int st = it & 1;
    const bool more = (it + 1) < DK / 16;

    if (more) {
      const int k0n = (it + 1) * 16;
      a0 = *(const float4*)(Aptr + k0n);
      a1 = *(const float4*)(Aptr + k0n + 4);
      b0 = *(const float4*)(Bptr + (size_t)k0n * N);
      b1 = *(const float4*)(Bptr + (size_t)k0n * N + 4);
    }

#pragma unroll
    for (int kk = 0; kk < 16; kk++) {
      ulonglong2 aA = *(const ulonglong2*)&sm.As[st][kk][ty * 8];
      ulonglong2 aB = *(const ulonglong2*)&sm.As[st][kk][ty * 8 + 4];
      const unsigned long long ap[4] = {aA.x, aA.y, aB.x, aB.y};
      float4 c0 = *(const float4*)&sm.Bs[st][kk][tx * 8];
      float4 c1 = *(const float4*)&sm.Bs[st][kk][tx * 8 + 4];
      const unsigned long long bb[8] = {
        bcast2(c0.x), bcast2(c0.y), bcast2(c0.z), bcast2(c0.w),
        bcast2(c1.x), bcast2(c1.y), bcast2(c1.z), bcast2(c1.w)};
#pragma unroll
      for (int ip = 0; ip < 4; ip++)
#pragma unroll
        for (int j = 0; j < 8; j++) fma2(acc2[ip][j], ap[ip], bb[j]);
    }

    if (more) {
      const int sn = st ^ 1;
      const float av[8] = {a0.x,a0.y,a0.z,a0.w, a1.x,a1.y,a1.z,a1.w};
#pragma unroll
      for (int u = 0; u < 8; u++) sm.As[sn][aKq + u][aRow] = av[u];
      *(float4*)&sm.Bs[sn][bK][bNq] = b0;
      *(float4*)&sm.Bs[sn][bK][bNq + 4] = b1;
    }
    __syncthreads();
  }

  if (mode == 0) {
#pragma unroll
    for (int i = 0; i < 4; i++) {
      const int m = m0 + ty * 8 + 2 * i;
#pragma unroll
      for (int j = 0; j < 8; j++) {
        float2 u = unpack2(acc2[i][j]);
        Cout[(size_t)m * N + n0 + tx * 8 + j] = u.x;
        Cout[(size_t)(m + 1) * N + n0 + tx * 8 + j] = u.y;
      }
    }
  } else if (!rope) {
    // V: scatter to [B, H, S, 64]; this block covers heads hbase, hbase+1
#pragma unroll
    for (int i = 0; i < 4; i++) {
      const int m = m0 + ty * 8 + 2 * i;
      const int bb_ = m >> 11, s = m & (SQ - 1);
#pragma unroll
      for (int j = 0; j < 8; j++) {
        const int d128 = tx * 8 + j;
        const int head = hbase + (d128 >> 6);
        const int d = d128 & 63;
        float2 u = unpack2(acc2[i][j]);
        Cout[(((size_t)bb_ * H + head) * SQ + s) * HD + d] = u.x;
        Cout[(((size_t)bb_ * H + head) * SQ + s + 1) * HD + d] = u.y;
      }
    }
  } else {
    // RoPE: partner col d^32 lives in lane^4 (same warp) -> shfl, no smem.
#pragma unroll
    for (int i = 0; i < 4; i++) {
      const int m = m0 + ty * 8 + 2 * i;
      const int bb_ = m >> 11, s = m & (SQ - 1);
#pragma unroll
      for (int j = 0; j < 8; j++) {
        const int d128 = tx * 8 + j;
        const int head = hbase + (d128 >> 6);
        const int d = d128 & 63;
        const int jj = d & 31;
        unsigned long long part = __shfl_xor_sync(0xffffffffu, acc2[i][j], 4);
        const float c_0 = rc[s * 32 + jj],  c_1 = rc[(s + 1) * 32 + jj];
        const float s_0 = rs[s * 32 + jj],  s_1 = rs[(s + 1) * 32 + jj];
        const unsigned long long c2 = pack2(c_0, c_1);
        const unsigned long long s2 = (d < 32) ? pack2(-s_0, -s_1)
                                               : pack2(s_0, s_1);
        mul2(part, s2);              // part = partner * (+-sin)
        fma2(part, acc2[i][j], c2);  // part += mine * cos
        float2 r = unpack2(part);
        Cout[(((size_t)bb_ * H + head) * SQ + s) * HD + d] = r.x;
        Cout[(((size_t)bb_ * H + head) * SQ + s + 1) * HD + d] = r.y;
      }
    }
  }
}

// ---------------------------------------------------------------------------
// Flash attention (unchanged from the measured-3079 version)
// ---------------------------------------------------------------------------
#define ATTN_SMEM_FLOATS (64 * 68 + 64 * 68)
#define ATTN_SMEM_BYTES  (ATTN_SMEM_FLOATS * 4)

__global__ void __launch_bounds__(64)
attn_kernel(const float* __restrict__ q, const float* __restrict__ k,
            const float* __restrict__ v, float* __restrict__ ao)
{
  extern __shared__ float smf[];
  float* qs = smf;                     // 64*68
  float* kv = smf + 64 * 68;           // 64*68

  const int t  = threadIdx.x;
  const int qt = gridDim.x - 1 - blockIdx.x;
  const int h  = blockIdx.y;
  const int b  = blockIdx.z;
  const int s0 = qt * 64;

  const float* qbase = q + (((size_t)b * NH + h) * SQ + s0) * HD;
  const size_t kvoff = ((size_t)b * NKV + (h >> 2)) * SQ * HD;
  const float* kbase = k + kvoff;
  const float* vbase = v + kvoff;

#pragma unroll 8
  for (int i = 0; i < 64; i++) qs[i * 68 + t] = qbase[i * HD + t];

  unsigned long long o2[32];
#pragma unroll
  for (int i = 0; i < 32; i++) o2[i] = 0ull;
  float mprev = -1e30f, l = 0.f;
  const int rg = s0 + t;

  for (int kt = 0; kt <= qt; kt++) {
    const int c0 = kt * 64;
    __syncthreads();
#pragma unroll 8
    for (int i = 0; i < 64; i++) kv[t * 68 + i] = kbase[(size_t)(c0 + i) * HD + t];
    __syncthreads();

    unsigned long long sc2[32];
#pragma unroll
    for (int i = 0; i < 32; i++) sc2[i] = 0ull;
#pragma unroll 2
    for (int d4 = 0; d4 < 16; d4++) {
      const float4 qv = *(const float4*)(qs + t * 68 + d4 * 4);
      const float qsc[4] = {qv.x, qv.y, qv.z, qv.w};
#pragma unroll
      for (int du = 0; du < 4; du++) {
        const int d = d4 * 4 + du;
        const unsigned long long qq = bcast2(qsc[du]);
#pragma unroll
        for (int cc = 0; cc < 16; cc++) {
          ulonglong2 kp = *(const ulonglong2*)(kv + d * 68 + cc * 4);
          fma2(sc2[cc * 2], kp.x, qq);
          fma2(sc2[cc * 2 + 1], kp.y, qq);
        }
      }
    }
    __syncthreads();

#pragma unroll 8
    for (int i = 0; i < 64; i++) kv[i * 68 + t] = vbase[(size_t)(c0 + i) * HD + t];

    float mnew = mprev;
    if (kt == qt) {
#pragma unroll
      for (int pi = 0; pi < 32; pi++) {
        float2 s = unpack2(sc2[pi]);
        float a0 = (c0 + 2 * pi     <= rg) ? s.x * 0.125f : -1e30f;
        float a1 = (c0 + 2 * pi + 1 <= rg) ? s.y * 0.125f : -1e30f;
        sc2[pi] = pack2(a0, a1);
        mnew = fmaxf(mnew, fmaxf(a0, a1));
      }
    } else {
#pragma unroll
      for (int pi = 0; pi < 32; pi++) {
        float2 s = unpack2(sc2[pi]);
        float a0 = s.x * 0.125f, a1 = s.y * 0.125f;
        sc2[pi] = pack2(a0, a1);
        mnew = fmaxf(mnew, fmaxf(a0, a1));
      }
    }
    const float corr = __expf(mprev - mnew);
    l *= corr;
    const unsigned long long cc2 = bcast2(corr);
#pragma unroll
    for (int i = 0; i < 32; i++) mul2(o2[i], cc2);

    float lsum = 0.f;
#pragma unroll
    for (int pi = 0; pi < 32; pi++) {
      float2 s = unpack2(sc2[pi]);
      const float p0 = __expf(s.x - mnew);
      const float p1 = __expf(s.y - mnew);
      lsum += p0 + p1;
      sc2[pi] = pack2(p0, p1);
    }
    l += lsum;
    mprev = mnew;
    __syncthreads();

#pragma unroll
    for (int pi = 0; pi < 32; pi++) {
      float2 pr = unpack2(sc2[pi]);
      const unsigned long long pp0 = bcast2(pr.x);
      const unsigned long long pp1 = bcast2(pr.y);
      const float* v0 = kv + (2 * pi) * 68;
      const float* v1 = kv + (2 * pi + 1) * 68;
#pragma unroll
      for (int dd = 0; dd < 16; dd++) {
        ulonglong2 vp = *(const ulonglong2*)(v0 + dd * 4);
        fma2(o2[dd * 2], vp.x, pp0);
        fma2(o2[dd * 2 + 1], vp.y, pp0);
      }
#pragma unroll
      for (int dd = 0; dd < 16; dd++) {
        ulonglong2 vp = *(const ulonglong2*)(v1 + dd * 4);
        fma2(o2[dd * 2], vp.x, pp1);
        fma2(o2[dd * 2 + 1], vp.y, pp1);
      }
    }
  }

  const float inv = 1.f / l;
  float* outp = ao + ((size_t)(b * SQ + s0 + t)) * (NH * HD) + h * HD;
#pragma unroll
  for (int pi = 0; pi < 32; pi++) {
    float2 u = unpack2(o2[pi]);
    *(float2*)(outp + 2 * pi) = make_float2(u.x * inv, u.y * inv);
  }
}

// ---------------------------------------------------------------------------
// Launch: fused QKV proj -> attention -> O proj
// ---------------------------------------------------------------------------
extern "C" void kernel_launch(void* const* d_in, const int* in_sizes, int n_in,
                              void* d_out, int out_size)
{
  const float* x  = (const float*)d_in[0];
  const float* Wq = (const float*)d_in[1];
  const float* Wk = (const float*)d_in[2];
  const float* Wv = (const float*)d_in[3];
  const float* Wo = (const float*)d_in[4];
  const float* rc = (const float*)d_in[5];
  const float* rs = (const float*)d_in[6];
  float* out = (float*)d_out;

  float *gq, *gk, *gv, *gao;
  cudaGetSymbolAddress((void**)&gq,  g_q);
  cudaGetSymbolAddress((void**)&gk,  g_k);
  cudaGetSymbolAddress((void**)&gv,  g_v);
  cudaGetSymbolAddress((void**)&gao, g_ao);

  cudaFuncSetAttribute(attn_kernel, cudaFuncAttributeMaxDynamicSharedMemorySize,
                       ATTN_SMEM_BYTES);

  // fused Q (rope) + K (rope) + V projections: 24 blocks x 32 m-tiles
  gemm128x128<<<dim3(24, 32), 256>>>(x, Wq, Wk, Wv, gq, gk, gv, rc, rs, 4);
  // attention
  attn_kernel<<<dim3(SQ / 64, NH, NB), 64, ATTN_SMEM_BYTES>>>(gq, gk, gv, gao);
  // output projection -> d_out (N = 128 * 16 = 2048)
  gemm128x128<<<dim3(16, 32), 256>>>(gao, Wo, nullptr, nullptr, out, nullptr,
                                     nullptr, nullptr, nullptr, 0);
}

// round 17
// speedup vs baseline: 1.1996x; 1.1996x over previous
#include <cuda_runtime.h>
#include <cstdint>
#include <cstddef>

// Problem constants
#define SQ 2048      // sequence length
#define DK 2048      // d_model (GEMM K dim)
#define NB 2         // batch
#define NH 32        // q heads
#define NKV 8        // kv heads
#define HD 64        // head dim

// Scratch (device globals: no runtime allocation allowed)
__device__ float g_q [(size_t)NB * NH  * SQ * HD];
__device__ float g_k [(size_t)NB * NKV * SQ * HD];
__device__ float g_v [(size_t)NB * NKV * SQ * HD];
__device__ float g_ao[(size_t)NB * SQ * NH * HD];

// ---------------------------------------------------------------------------
// Packed f32x2 helpers (sm_103a: PTX-only FFMA2 path)
// ---------------------------------------------------------------------------
__device__ __forceinline__ unsigned long long bcast2(float x) {
  unsigned long long r;
  unsigned int u = __float_as_uint(x);
  asm("mov.b64 %0, {%1, %1};" : "=l"(r) : "r"(u));
  return r;
}
__device__ __forceinline__ unsigned long long pack2(float x, float y) {
  unsigned long long r;
  asm("mov.b64 %0, {%1, %2};" : "=l"(r)
      : "r"(__float_as_uint(x)), "r"(__float_as_uint(y)));
  return r;
}
__device__ __forceinline__ void fma2(unsigned long long& d,
                                     unsigned long long a,
                                     unsigned long long b) {
  asm("fma.rn.f32x2 %0, %1, %2, %0;" : "+l"(d) : "l"(a), "l"(b));
}
__device__ __forceinline__ void mul2(unsigned long long& d,
                                     unsigned long long a) {
  asm("mul.rn.f32x2 %0, %0, %1;" : "+l"(d) : "l"(a));
}
__device__ __forceinline__ float2 unpack2(unsigned long long v) {
  unsigned int lo, hi;
  asm("mov.b64 {%0, %1}, %2;" : "=r"(lo), "=r"(hi) : "l"(v));
  return make_float2(__uint_as_float(lo), __uint_as_float(hi));
}

// ---------------------------------------------------------------------------
// GEMM (measured-best config): BM=128, BN=64, BK=16, 256 threads,
// 8x4 micro-tile, LDG.128 loaders, register prefetch, 2-stage double buffer.
// regs=80 -> 3 blocks/SM (24 warps), fma 65%, L1 87% (measured). UNCHANGED.
// mode 0: plain row-major write to C (O projection), N = full row width
// mode 4: fused QKV — blockIdx.x in [0,32): Q (rope), [32,40): K (rope),
//                                  [40,48): V (plain)
// ---------------------------------------------------------------------------
struct GemmSmem {
  union {
    struct { float As[2][16][132]; float Bs[2][16][68]; } ab;  // As is [k][m]
    float Cs[128][65];                                          // epilogue staging
  };
};

__global__ void __launch_bounds__(256)
gemm128x64(const float* __restrict__ A,
           const float* __restrict__ Wq, const float* __restrict__ Wk,
           const float* __restrict__ Wv,
           float* __restrict__ Cq, float* __restrict__ Ck,
           float* __restrict__ Cv,
           const float* __restrict__ rc, const float* __restrict__ rs, int mode)
{
  __shared__ GemmSmem sm;
  const int tid = threadIdx.x;
  const int tx = tid & 15;        // 16 col-groups of 4
  const int ty = tid >> 4;        // 16 row-groups of 8
  const int m0 = blockIdx.y * 128;

  int hx = blockIdx.x;
  bool rope = false;
  const float* W = Wq;
  float* Cout = Cq;
  int H = NH;
  int N = 64 * gridDim.x;          // mode 0: full row width
  if (mode == 4) {
    if (hx < 32)      { W = Wq; Cout = Cq; H = NH;  rope = true;  N = 2048; }
    else if (hx < 40) { hx -= 32; W = Wk; Cout = Ck; H = NKV; rope = true;  N = 512; }
    else              { hx -= 40; W = Wv; Cout = Cv; H = NKV; rope = false; N = 512; }
  }
  const int n0 = hx * 64;

  unsigned long long acc2[4][4];
#pragma unroll
  for (int i = 0; i < 4; i++)
#pragma unroll
    for (int j = 0; j < 4; j++) acc2[i][j] = 0ull;

  const int aRow = tid >> 2;
  const int aKq  = (tid & 3) * 4;
  const int bK   = tid >> 4;
  const int bNq  = (tid & 15) * 4;

  const float* Aptr = A + (size_t)(m0 + aRow) * DK + aKq;
  const float* Bptr = W + (size_t)bK * N + n0 + bNq;

  float4 av0 = *(const float4*)(Aptr);
  float4 av1 = *(const float4*)(Aptr + (size_t)64 * DK);
  float4 bv  = *(const float4*)(Bptr);

  sm.ab.As[0][aKq + 0][aRow] = av0.x;
  sm.ab.As[0][aKq + 1][aRow] = av0.y;
  sm.ab.As[0][aKq + 2][aRow] = av0.z;
  sm.ab.As[0][aKq + 3][aRow] = av0.w;
  sm.ab.As[0][aKq + 0][aRow + 64] = av1.x;
  sm.ab.As[0][aKq + 1][aRow + 64] = av1.y;
  sm.ab.As[0][aKq + 2][aRow + 64] = av1.z;
  sm.ab.As[0][aKq + 3][aRow + 64] = av1.w;
  *(float4*)&sm.ab.Bs[0][bK][bNq] = bv;
  __syncthreads();

  for (int it = 0; it < DK / 16; it++) {
    const int st = it & 1;
    const bool more = (it + 1) < DK / 16;

    if (more) {
      const int k0n = (it + 1) * 16;
      av0 = *(const float4*)(Aptr + k0n);
      av1 = *(const float4*)(Aptr + (size_t)64 * DK + k0n);
      bv  = *(const float4*)(Bptr + (size_t)k0n * N);
    }

#pragma unroll
    for (int kk = 0; kk < 16; kk++) {
      ulonglong2 aA = *(const ulonglong2*)&sm.ab.As[st][kk][ty * 8];
      ulonglong2 aB = *(const ulonglong2*)&sm.ab.As[st][kk][ty * 8 + 4];
      float4 b4 = *(const float4*)&sm.ab.Bs[st][kk][tx * 4];
      unsigned long long bb0 = bcast2(b4.x), bb1 = bcast2(b4.y);
      unsigned long long bb2 = bcast2(b4.z), bb3 = bcast2(b4.w);
      fma2(acc2[0][0], aA.x, bb0); fma2(acc2[0][1], aA.x, bb1);
      fma2(acc2[0][2], aA.x, bb2); fma2(acc2[0][3], aA.x, bb3);
      fma2(acc2[1][0], aA.y, bb0); fma2(acc2[1][1], aA.y, bb1);
      fma2(acc2[1][2], aA.y, bb2); fma2(acc2[1][3], aA.y, bb3);
      fma2(acc2[2][0], aB.x, bb0); fma2(acc2[2][1], aB.x, bb1);
      fma2(acc2[2][2], aB.x, bb2); fma2(acc2[2][3], aB.x, bb3);
      fma2(acc2[3][0], aB.y, bb0); fma2(acc2[3][1], aB.y, bb1);
      fma2(acc2[3][2], aB.y, bb2); fma2(acc2[3][3], aB.y, bb3);
    }

    if (more) {
      const int sn = st ^ 1;
      sm.ab.As[sn][aKq + 0][aRow] = av0.x;
      sm.ab.As[sn][aKq + 1][aRow] = av0.y;
      sm.ab.As[sn][aKq + 2][aRow] = av0.z;
      sm.ab.As[sn][aKq + 3][aRow] = av0.w;
      sm.ab.As[sn][aKq + 0][aRow + 64] = av1.x;
      sm.ab.As[sn][aKq + 1][aRow + 64] = av1.y;
      sm.ab.As[sn][aKq + 2][aRow + 64] = av1.z;
      sm.ab.As[sn][aKq + 3][aRow + 64] = av1.w;
      *(float4*)&sm.ab.Bs[sn][bK][bNq] = bv;
    }
    __syncthreads();
  }

  if (mode == 0) {
#pragma unroll
    for (int i = 0; i < 4; i++) {
      const int m = m0 + ty * 8 + 2 * i;
#pragma unroll
      for (int j = 0; j < 4; j++) {
        float2 u = unpack2(acc2[i][j]);
        Cout[(size_t)m * N + n0 + tx * 4 + j] = u.x;
        Cout[(size_t)(m + 1) * N + n0 + tx * 4 + j] = u.y;
      }
    }
  } else if (!rope) {
#pragma unroll
    for (int i = 0; i < 4; i++) {
      const int m = m0 + ty * 8 + 2 * i;
      const int bb = m >> 11, s = m & (SQ - 1);
#pragma unroll
      for (int j = 0; j < 4; j++) {
        const int d = tx * 4 + j;
        float2 u = unpack2(acc2[i][j]);
        Cout[(((size_t)bb * H + hx) * SQ + s) * HD + d] = u.x;
        Cout[(((size_t)bb * H + hx) * SQ + s + 1) * HD + d] = u.y;
      }
    }
  } else {
#pragma unroll
    for (int i = 0; i < 4; i++)
#pragma unroll
      for (int j = 0; j < 4; j++) {
        float2 u = unpack2(acc2[i][j]);
        sm.Cs[ty * 8 + 2 * i][tx * 4 + j] = u.x;
        sm.Cs[ty * 8 + 2 * i + 1][tx * 4 + j] = u.y;
      }
    __syncthreads();
#pragma unroll
    for (int i = 0; i < 8; i++) {
      const int m = m0 + ty * 8 + i;
      const int bb = m >> 11, s = m & (SQ - 1);
#pragma unroll
      for (int j = 0; j < 4; j++) {
        const int d = tx * 4 + j;
        const int jj = d & 31;
        const float c = rc[s * 32 + jj];
        const float sn = rs[s * 32 + jj];
        float res;
        if (d < 32)
          res = sm.Cs[ty * 8 + i][d] * c - sm.Cs[ty * 8 + i][d + 32] * sn;
        else
          res = sm.Cs[ty * 8 + i][d - 32] * sn + sm.Cs[ty * 8 + i][d] * c;
        Cout[(((size_t)bb * H + hx) * SQ + s) * HD + d] = res;
      }
    }
  }
}

// ---------------------------------------------------------------------------
// Flash attention. K-tile transpose store was 4-way bank conflicted (lanes
// t, t+8, t+16, t+24 share a bank at stride 68). Fix: XOR swizzle chunk bits
// with the storing row's bits 3-4:
//   store  kv[t*68 + (i ^ (t & 24))]
//   read   kv[d*68 + ((cc*4) ^ (d & 24))]   (broadcast, 16B-aligned)
// QK d-loop fully unrolled so the swizzled offsets fold into immediates.
// V store/read and Q store/read are conflict-free and stay unswizzled.
// ---------------------------------------------------------------------------
#define ATTN_SMEM_FLOATS (64 * 68 + 64 * 68)
#define ATTN_SMEM_BYTES  (ATTN_SMEM_FLOATS * 4)

__global__ void __launch_bounds__(64)
attn_kernel(const float* __restrict__ q, const float* __restrict__ k,
            const float* __restrict__ v, float* __restrict__ ao)
{
  extern __shared__ float smf[];
  float* qs = smf;                     // 64*68
  float* kv = smf + 64 * 68;           // 64*68

  const int t  = threadIdx.x;
  const int qt = gridDim.x - 1 - blockIdx.x;  // heavy tiles launch first
  const int h  = blockIdx.y;
  const int b  = blockIdx.z;
  const int s0 = qt * 64;

  const float* qbase = q + (((size_t)b * NH + h) * SQ + s0) * HD;
  const size_t kvoff = ((size_t)b * NKV + (h >> 2)) * SQ * HD;
  const float* kbase = k + kvoff;
  const float* vbase = v + kvoff;

#pragma unroll 8
  for (int i = 0; i < 64; i++) qs[i * 68 + t] = qbase[i * HD + t];

  unsigned long long o2[32];
#pragma unroll
  for (int i = 0; i < 32; i++) o2[i] = 0ull;
  float mprev = -1e30f, l = 0.f;
  const int rg = s0 + t;
  const int tsw = t & 24;              // K-store swizzle for this thread's row

  for (int kt = 0; kt <= qt; kt++) {
    const int c0 = kt * 64;
    __syncthreads();
    // K tile transposed + swizzled: ksT[d=t][c] ; conflict-free STS
#pragma unroll 8
    for (int i = 0; i < 64; i++)
      kv[t * 68 + (i ^ tsw)] = kbase[(size_t)(c0 + i) * HD + t];
    __syncthreads();

    // QK: fully unrolled so swizzled chunk offsets are immediates
    unsigned long long sc2[32];
#pragma unroll
    for (int i = 0; i < 32; i++) sc2[i] = 0ull;
#pragma unroll
    for (int d4 = 0; d4 < 16; d4++) {
      const float4 qv = *(const float4*)(qs + t * 68 + d4 * 4);
      const float qsc[4] = {qv.x, qv.y, qv.z, qv.w};
#pragma unroll
      for (int du = 0; du < 4; du++) {
        const int d = d4 * 4 + du;
        const int dsw = d & 24;
        const unsigned long long qq = bcast2(qsc[du]);
#pragma unroll
        for (int cc = 0; cc < 16; cc++) {
          ulonglong2 kp = *(const ulonglong2*)(kv + d * 68 + ((cc * 4) ^ dsw));
          fma2(sc2[cc * 2], kp.x, qq);
          fma2(sc2[cc * 2 + 1], kp.y, qq);
        }
      }
    }
    __syncthreads();

    // overwrite kv with V tile (unswizzled): vs[c=i][d=t]
#pragma unroll 8
    for (int i = 0; i < 64; i++) kv[i * 68 + t] = vbase[(size_t)(c0 + i) * HD + t];

    float mnew = mprev;
    if (kt == qt) {
#pragma unroll
      for (int pi = 0; pi < 32; pi++) {
        float2 s = unpack2(sc2[pi]);
        float a0 = (c0 + 2 * pi     <= rg) ? s.x * 0.125f : -1e30f;
        float a1 = (c0 + 2 * pi + 1 <= rg) ? s.y * 0.125f : -1e30f;
        sc2[pi] = pack2(a0, a1);
        mnew = fmaxf(mnew, fmaxf(a0, a1));
      }
    } else {
#pragma unroll
      for (int pi = 0; pi < 32; pi++) {
        float2 s = unpack2(sc2[pi]);
        float a0 = s.x * 0.125f, a1 = s.y * 0.125f;
        sc2[pi] = pack2(a0, a1);
        mnew = fmaxf(mnew, fmaxf(a0, a1));
      }
    }
    const float corr = __expf(mprev - mnew);
    l *= corr;
    const unsigned long long cc2 = bcast2(corr);
#pragma unroll
    for (int i = 0; i < 32; i++) mul2(o2[i], cc2);

    float lsum = 0.f;
#pragma unroll
    for (int pi = 0; pi < 32; pi++) {
      float2 s = unpack2(sc2[pi]);
      const float p0 = __expf(s.x - mnew);
      const float p1 = __expf(s.y - mnew);
      lsum += p0 + p1;
      sc2[pi] = pack2(p0, p1);
    }
    l += lsum;
    mprev = mnew;
    __syncthreads();

    // PV: probs in registers, fully unrolled
#pragma unroll
    for (int pi = 0; pi < 32; pi++) {
      float2 pr = unpack2(sc2[pi]);
      const unsigned long long pp0 = bcast2(pr.x);
      const unsigned long long pp1 = bcast2(pr.y);
      const float* v0 = kv + (2 * pi) * 68;
      const float* v1 = kv + (2 * pi + 1) * 68;
#pragma unroll
      for (int dd = 0; dd < 16; dd++) {
        ulonglong2 vp = *(const ulonglong2*)(v0 + dd * 4);
        fma2(o2[dd * 2], vp.x, pp0);
        fma2(o2[dd * 2 + 1], vp.y, pp0);
      }
#pragma unroll
      for (int dd = 0; dd < 16; dd++) {
        ulonglong2 vp = *(const ulonglong2*)(v1 + dd * 4);
        fma2(o2[dd * 2], vp.x, pp1);
        fma2(o2[dd * 2 + 1], vp.y, pp1);
      }
    }
  }

  const float inv = 1.f / l;
  float* outp = ao + ((size_t)(b * SQ + s0 + t)) * (NH * HD) + h * HD;
#pragma unroll
  for (int pi = 0; pi < 32; pi++) {
    float2 u = unpack2(o2[pi]);
    *(float2*)(outp + 2 * pi) = make_float2(u.x * inv, u.y * inv);
  }
}

// ---------------------------------------------------------------------------
// Launch: fused QKV proj -> attention -> O proj
// ---------------------------------------------------------------------------
extern "C" void kernel_launch(void* const* d_in, const int* in_sizes, int n_in,
                              void* d_out, int out_size)
{
  const float* x  = (const float*)d_in[0];
  const float* Wq = (const float*)d_in[1];
  const float* Wk = (const float*)d_in[2];
  const float* Wv = (const float*)d_in[3];
  const float* Wo = (const float*)d_in[4];
  const float* rc = (const float*)d_in[5];
  const float* rs = (const float*)d_in[6];
  float* out = (float*)d_out;

  float *gq, *gk, *gv, *gao;
  cudaGetSymbolAddress((void**)&gq,  g_q);
  cudaGetSymbolAddress((void**)&gk,  g_k);
  cudaGetSymbolAddress((void**)&gv,  g_v);
  cudaGetSymbolAddress((void**)&gao, g_ao);

  cudaFuncSetAttribute(attn_kernel, cudaFuncAttributeMaxDynamicSharedMemorySize,
                       ATTN_SMEM_BYTES);

  // fused Q (rope) + K (rope) + V projections: 48 head-blocks x 32 m-tiles
  gemm128x64<<<dim3(48, 32), 256>>>(x, Wq, Wk, Wv, gq, gk, gv, rc, rs, 4);
  // attention
  attn_kernel<<<dim3(SQ / 64, NH, NB), 64, ATTN_SMEM_BYTES>>>(gq, gk, gv, gao);
  // output projection -> d_out (N = 64 * 32 = 2048)
  gemm128x64<<<dim3(32, 32), 256>>>(gao, Wo, nullptr, nullptr, out, nullptr,
                                    nullptr, nullptr, nullptr, 0);
}